// round 1
// baseline (speedup 1.0000x reference)
#include <cuda_runtime.h>
#include <cuda_bf16.h>
#include <math.h>

// ---------------- problem constants ----------------
#define B_   4
#define S1_  768
#define S2_  64
#define S_   832
#define D0_  2048
#define F0_  16384
#define D1_  1024
#define F1_  4096
#define H_   8
#define HD_  256
#define EPS_ 1e-6f
#define MASK_VAL_ -1000000000.0f

// ---------------- scratch (device globals; no allocation allowed) ----------------
__device__ float g_h0[B_*S1_*D0_];
__device__ float g_h1[B_*S2_*D1_];
__device__ float g_mod_in[B_*2*D1_];
__device__ float g_mod_post[B_*2*D1_];
__device__ float g_q[(size_t)B_*S_*H_*HD_];
__device__ float g_k[B_*S_*HD_];
__device__ float g_v[B_*S_*HD_];
__device__ float g_scores[(size_t)B_*H_*S_*S_];
__device__ float g_att[(size_t)B_*S_*H_*HD_];
__device__ float g_r0[B_*S1_*D0_];
__device__ float g_y0[B_*S1_*D0_];
__device__ float g_gu0[(size_t)B_*S1_*F0_];
__device__ float g_r1[B_*S2_*D1_];
__device__ float g_y1[B_*S2_*D1_];
__device__ float g_gu1[B_*S2_*F1_];
__device__ int   g_pos[B_*S_];
__device__ int   g_cs[B_*S_];

// ---------------- small helpers ----------------
__device__ __forceinline__ float gelu_tanh(float x) {
    float x3 = x * x * x;
    return 0.5f * x * (1.0f + tanhf(0.79788456080286535588f * (x + 0.044715f * x3)));
}

// ---------------- generic batched SGEMM with fused epilogues ----------------
// C[z] = A[z] @ B[z]  (optionally B transposed), z in [0, gridDim.z)
// per-z offsets: off = (z/zdiv)*s1 + (z%zdiv)*s2
#define EPI_NONE     0
#define EPI_SCORES   1   // v = allowed ? v*scale : MASK_VAL
#define EPI_RES      2   // v = aux + v
#define EPI_RES_GATE 3   // v = aux + gvec[col]*v
#define EPI_GELUMUL  4   // v = gelu(aux) * v   (aux may alias C)

struct GemmP {
    const float* A; const float* B; float* C;
    int M, N, K, lda, ldb, ldc;
    long sA1, sA2, sB1, sB2, sC1, sC2;
    int zdiv;
    int transB;
    int epi;
    const float* aux; long sAux;
    const float* gvec; int gvecStride;
    const int* cs; const int* pad; int maskStride;
    float scale;
};

#define BM 128
#define BN 128
#define BK 8
#define TM 8
#define TN 8

__global__ __launch_bounds__(256) void gemm_kernel(GemmP p) {
    __shared__ float As[BK][BM];
    __shared__ float Bs[BK][BN];

    int z  = blockIdx.z;
    int zb = z / p.zdiv;
    int zr = z % p.zdiv;

    const float* A = p.A + (long)zb * p.sA1 + (long)zr * p.sA2;
    const float* Bm = p.B + (long)zb * p.sB1 + (long)zr * p.sB2;
    float* C = p.C + (long)zb * p.sC1 + (long)zr * p.sC2;

    int rowBase = blockIdx.y * BM;
    int colBase = blockIdx.x * BN;
    int tid = threadIdx.x;
    int tx = tid % 16;
    int ty = tid / 16;

    float acc[TM][TN];
    #pragma unroll
    for (int i = 0; i < TM; i++)
        #pragma unroll
        for (int j = 0; j < TN; j++) acc[i][j] = 0.0f;

    // A tile loader: 128 rows x 8 cols. thread -> row tid/2, col (tid%2)*4
    int aRow = tid >> 1;
    int aCol = (tid & 1) * 4;
    // B tile loader (NN): 8 rows x 128 cols. thread -> row tid/32, col (tid%32)*4
    int bRow = tid >> 5;
    int bCol = (tid & 31) * 4;

    for (int k0 = 0; k0 < p.K; k0 += BK) {
        // ---- load A (K assumed multiple of 8) ----
        {
            int gr = rowBase + aRow;
            float4 av = make_float4(0.f, 0.f, 0.f, 0.f);
            if (gr < p.M)
                av = *(const float4*)&A[(long)gr * p.lda + k0 + aCol];
            As[aCol + 0][aRow] = av.x;
            As[aCol + 1][aRow] = av.y;
            As[aCol + 2][aRow] = av.z;
            As[aCol + 3][aRow] = av.w;
        }
        // ---- load B ----
        if (!p.transB) {
            int gk = k0 + bRow;
            int gc = colBase + bCol;
            if (gc + 3 < p.N) {
                float4 bv = *(const float4*)&Bm[(long)gk * p.ldb + gc];
                Bs[bRow][bCol + 0] = bv.x;
                Bs[bRow][bCol + 1] = bv.y;
                Bs[bRow][bCol + 2] = bv.z;
                Bs[bRow][bCol + 3] = bv.w;
            } else {
                #pragma unroll
                for (int i = 0; i < 4; i++)
                    Bs[bRow][bCol + i] = (gc + i < p.N) ? Bm[(long)gk * p.ldb + gc + i] : 0.f;
            }
        } else {
            // Bs[k][n] = B[(colBase+n)*ldb + k0+k]
            int n  = tid >> 1;
            int kk = (tid & 1) * 4;
            int gn = colBase + n;
            float4 bv = make_float4(0.f, 0.f, 0.f, 0.f);
            if (gn < p.N)
                bv = *(const float4*)&Bm[(long)gn * p.ldb + k0 + kk];
            Bs[kk + 0][n] = bv.x;
            Bs[kk + 1][n] = bv.y;
            Bs[kk + 2][n] = bv.z;
            Bs[kk + 3][n] = bv.w;
        }
        __syncthreads();

        #pragma unroll
        for (int k = 0; k < BK; k++) {
            float a[TM], b[TN];
            float4 a0 = *(const float4*)&As[k][ty * TM];
            float4 a1 = *(const float4*)&As[k][ty * TM + 4];
            a[0]=a0.x; a[1]=a0.y; a[2]=a0.z; a[3]=a0.w;
            a[4]=a1.x; a[5]=a1.y; a[6]=a1.z; a[7]=a1.w;
            float4 b0 = *(const float4*)&Bs[k][tx * TN];
            float4 b1 = *(const float4*)&Bs[k][tx * TN + 4];
            b[0]=b0.x; b[1]=b0.y; b[2]=b0.z; b[3]=b0.w;
            b[4]=b1.x; b[5]=b1.y; b[6]=b1.z; b[7]=b1.w;
            #pragma unroll
            for (int i = 0; i < TM; i++)
                #pragma unroll
                for (int j = 0; j < TN; j++)
                    acc[i][j] += a[i] * b[j];
        }
        __syncthreads();
    }

    // ---- epilogue ----
    const int* csb  = p.cs  ? p.cs  + (long)zb * p.maskStride : nullptr;
    const int* padb = p.pad ? p.pad + (long)zb * p.maskStride : nullptr;
    long auxOff = (long)zb * p.sAux;

    #pragma unroll
    for (int i = 0; i < TM; i++) {
        int row = rowBase + ty * TM + i;
        if (row >= p.M) continue;
        #pragma unroll
        for (int j = 0; j < TN; j++) {
            int col = colBase + tx * TN + j;
            if (col >= p.N) continue;
            long idx = (long)row * p.ldc + col;
            float v = acc[i][j];
            if (p.epi == EPI_SCORES) {
                bool ok = (csb[col] <= csb[row]) && (padb[row] != 0) && (padb[col] != 0);
                v = ok ? v * p.scale : MASK_VAL_;
            } else if (p.epi == EPI_RES) {
                v += p.aux[auxOff + idx];
            } else if (p.epi == EPI_RES_GATE) {
                v = p.aux[auxOff + idx] + p.gvec[(long)zb * p.gvecStride + col] * v;
            } else if (p.epi == EPI_GELUMUL) {
                v = gelu_tanh(p.aux[auxOff + idx]) * v;
            }
            C[idx] = v;
        }
    }
}

// ---------------- mod GEMV: out[b, j] = bias[j] + sum_k cond[b,k] * W[k,j] ----------------
__global__ void mod_kernel(const float* __restrict__ cond, const float* __restrict__ W,
                           const float* __restrict__ bias, float* __restrict__ out,
                           int D, int N) {
    int j = blockIdx.x * blockDim.x + threadIdx.x;
    int b = blockIdx.y;
    if (j >= N) return;
    float s = bias[j];
    const float* c = cond + (long)b * D;
    for (int k = 0; k < D; k++)
        s += c[k] * W[(long)k * N + j];
    out[(long)b * N + j] = s;
}

// ---------------- prefix scans: pos = cumsum(pad)-1, cs = cumsum(att) ----------------
__global__ void scan_kernel(const int* __restrict__ pad, const int* __restrict__ att,
                            int* __restrict__ pos, int* __restrict__ cs) {
    int b = threadIdx.x;
    if (b >= B_) return;
    int cp = 0, ca = 0;
    for (int s = 0; s < S_; s++) {
        cp += pad[b * S_ + s];
        ca += att[b * S_ + s];
        pos[b * S_ + s] = cp - 1;
        cs[b * S_ + s] = ca;
    }
}

// ---------------- RMSNorm: out = x * rsqrt(mean(x^2)+eps) * (1 + w[b*wStride + d]) ----------------
__global__ void rmsnorm_kernel(const float* __restrict__ x, float* __restrict__ out,
                               const float* __restrict__ w, int wStride,
                               int D, int rowsPerBatch) {
    long row = blockIdx.x;
    int b = (int)(row / rowsPerBatch);
    const float* xp = x + row * (long)D;
    float ss = 0.f;
    for (int i = threadIdx.x; i < D; i += blockDim.x) {
        float v = xp[i];
        ss += v * v;
    }
    __shared__ float red[256];
    red[threadIdx.x] = ss;
    __syncthreads();
    for (int s = 128; s > 0; s >>= 1) {
        if (threadIdx.x < s) red[threadIdx.x] += red[threadIdx.x + s];
        __syncthreads();
    }
    float r = rsqrtf(red[0] / (float)D + EPS_);
    const float* wp = w + (long)b * wStride;
    float* op = out + row * (long)D;
    for (int i = threadIdx.x; i < D; i += blockDim.x)
        op[i] = xp[i] * r * (1.0f + wp[i]);
}

// ---------------- RoPE (in place). X layout: [B, S, nH*HD], pair (i, i+128) per head ----------------
__global__ void rope_kernel(float* __restrict__ X, const int* __restrict__ pos, int nH, long total) {
    long idx = blockIdx.x * (long)blockDim.x + threadIdx.x;
    if (idx >= total) return;
    int i = (int)(idx & 127);
    long t = idx >> 7;
    int h = (int)(t % nH); t /= nH;
    int s = (int)(t % S_);
    int b = (int)(t / S_);
    float p = (float)pos[b * S_ + s];
    float inv = expf(-((float)i / 128.0f) * 9.210340371976184f);  // 10000^(-i/128)
    float f = p * inv;
    float c = cosf(f), sn = sinf(f);
    float* base = X + ((long)(b * S_ + s) * nH + h) * (long)HD_;
    float x1 = base[i];
    float x2 = base[i + 128];
    base[i]       = x1 * c - x2 * sn;
    base[i + 128] = x2 * c + x1 * sn;
}

// ---------------- row softmax (fp32), row length S_ ----------------
__global__ void softmax_kernel(float* __restrict__ scores) {
    float* p = scores + (long)blockIdx.x * S_;
    __shared__ float red[256];
    int tid = threadIdx.x;

    float m = -3.4e38f;
    for (int i = tid; i < S_; i += 256) m = fmaxf(m, p[i]);
    red[tid] = m;
    __syncthreads();
    for (int s = 128; s > 0; s >>= 1) {
        if (tid < s) red[tid] = fmaxf(red[tid], red[tid + s]);
        __syncthreads();
    }
    m = red[0];
    __syncthreads();

    float sum = 0.f;
    for (int i = tid; i < S_; i += 256) {
        float e = expf(p[i] - m);
        p[i] = e;
        sum += e;
    }
    red[tid] = sum;
    __syncthreads();
    for (int s = 128; s > 0; s >>= 1) {
        if (tid < s) red[tid] += red[tid + s];
        __syncthreads();
    }
    float inv = 1.0f / red[0];
    for (int i = tid; i < S_; i += 256) p[i] *= inv;
}

// ---------------- host-side launch helper ----------------
static void launch_gemm(const float* A, const float* Bm, float* C,
                        int M, int N, int K, int lda, int ldb, int ldc,
                        int batches, long sA1, long sA2, long sB1, long sB2,
                        long sC1, long sC2, int zdiv, bool transB, int epi,
                        const float* aux = nullptr, long sAux = 0,
                        const float* gvec = nullptr, int gvecStride = 0,
                        const int* cs = nullptr, const int* pad = nullptr,
                        int maskStride = 0, float scale = 1.0f) {
    GemmP p;
    p.A = A; p.B = Bm; p.C = C;
    p.M = M; p.N = N; p.K = K; p.lda = lda; p.ldb = ldb; p.ldc = ldc;
    p.sA1 = sA1; p.sA2 = sA2; p.sB1 = sB1; p.sB2 = sB2; p.sC1 = sC1; p.sC2 = sC2;
    p.zdiv = zdiv; p.transB = transB ? 1 : 0; p.epi = epi;
    p.aux = aux; p.sAux = sAux; p.gvec = gvec; p.gvecStride = gvecStride;
    p.cs = cs; p.pad = pad; p.maskStride = maskStride; p.scale = scale;
    dim3 grid((N + BN - 1) / BN, (M + BM - 1) / BM, batches);
    gemm_kernel<<<grid, 256>>>(p);
}

extern "C" void kernel_launch(void* const* d_in, const int* in_sizes, int n_in,
                              void* d_out, int out_size) {
    const float* x0         = (const float*)d_in[0];
    const float* x1         = (const float*)d_in[1];
    const float* cond1      = (const float*)d_in[2];
    const float* w_q0       = (const float*)d_in[3];
    const float* w_k0       = (const float*)d_in[4];
    const float* w_v0       = (const float*)d_in[5];
    const float* w_o0       = (const float*)d_in[6];
    const float* norm1_w0   = (const float*)d_in[7];
    const float* norm2_w0   = (const float*)d_in[8];
    const float* w_gate0    = (const float*)d_in[9];
    const float* w_up0      = (const float*)d_in[10];
    const float* w_down0    = (const float*)d_in[11];
    const float* w_q1       = (const float*)d_in[12];
    const float* w_k1       = (const float*)d_in[13];
    const float* w_v1       = (const float*)d_in[14];
    const float* w_o1       = (const float*)d_in[15];
    const float* ada_in_w1  = (const float*)d_in[16];
    const float* ada_in_b1  = (const float*)d_in[17];
    const float* ada_post_w1= (const float*)d_in[18];
    const float* ada_post_b1= (const float*)d_in[19];
    const float* w_gate1    = (const float*)d_in[20];
    const float* w_up1      = (const float*)d_in[21];
    const float* w_down1    = (const float*)d_in[22];
    const int*   pad_masks  = (const int*)d_in[23];
    const int*   att_masks  = (const int*)d_in[24];

    float* out0 = (float*)d_out;
    float* out1 = out0 + (size_t)B_ * S1_ * D0_;

    float *h0, *h1, *modin, *modpost, *q, *k, *v, *scores, *att, *r0, *y0, *gu0, *r1, *y1, *gu1;
    int *pos, *cs;
    cudaGetSymbolAddress((void**)&h0, g_h0);
    cudaGetSymbolAddress((void**)&h1, g_h1);
    cudaGetSymbolAddress((void**)&modin, g_mod_in);
    cudaGetSymbolAddress((void**)&modpost, g_mod_post);
    cudaGetSymbolAddress((void**)&q, g_q);
    cudaGetSymbolAddress((void**)&k, g_k);
    cudaGetSymbolAddress((void**)&v, g_v);
    cudaGetSymbolAddress((void**)&scores, g_scores);
    cudaGetSymbolAddress((void**)&att, g_att);
    cudaGetSymbolAddress((void**)&r0, g_r0);
    cudaGetSymbolAddress((void**)&y0, g_y0);
    cudaGetSymbolAddress((void**)&gu0, g_gu0);
    cudaGetSymbolAddress((void**)&r1, g_r1);
    cudaGetSymbolAddress((void**)&y1, g_y1);
    cudaGetSymbolAddress((void**)&gu1, g_gu1);
    cudaGetSymbolAddress((void**)&pos, g_pos);
    cudaGetSymbolAddress((void**)&cs, g_cs);

    // 1) adaLN modulation vectors
    {
        dim3 mg((2 * D1_ + 255) / 256, B_);
        mod_kernel<<<mg, 256>>>(cond1, ada_in_w1,  ada_in_b1,  modin,   D1_, 2 * D1_);
        mod_kernel<<<mg, 256>>>(cond1, ada_post_w1, ada_post_b1, modpost, D1_, 2 * D1_);
    }

    // 2) position / mask cumulative sums
    scan_kernel<<<1, 32>>>(pad_masks, att_masks, pos, cs);

    // 3) input norms
    rmsnorm_kernel<<<B_ * S1_, 256>>>(x0, h0, norm1_w0, 0, D0_, S1_);
    rmsnorm_kernel<<<B_ * S2_, 256>>>(x1, h1, modin /*scale_in*/, 2 * D1_, D1_, S2_);

    // 4) QKV projections (stream 0 rows [0,768), stream 1 rows [768,832) of the S=832 buffers)
    launch_gemm(h0, w_q0, q, S1_, H_*HD_, D0_, D0_, H_*HD_, H_*HD_,
                B_, (long)S1_*D0_, 0, 0, 0, (long)S_*H_*HD_, 0, 1, false, EPI_NONE);
    launch_gemm(h0, w_k0, k, S1_, HD_, D0_, D0_, HD_, HD_,
                B_, (long)S1_*D0_, 0, 0, 0, (long)S_*HD_, 0, 1, false, EPI_NONE);
    launch_gemm(h0, w_v0, v, S1_, HD_, D0_, D0_, HD_, HD_,
                B_, (long)S1_*D0_, 0, 0, 0, (long)S_*HD_, 0, 1, false, EPI_NONE);
    launch_gemm(h1, w_q1, q + (long)S1_*H_*HD_, S2_, H_*HD_, D1_, D1_, H_*HD_, H_*HD_,
                B_, (long)S2_*D1_, 0, 0, 0, (long)S_*H_*HD_, 0, 1, false, EPI_NONE);
    launch_gemm(h1, w_k1, k + (long)S1_*HD_, S2_, HD_, D1_, D1_, HD_, HD_,
                B_, (long)S2_*D1_, 0, 0, 0, (long)S_*HD_, 0, 1, false, EPI_NONE);
    launch_gemm(h1, w_v1, v + (long)S1_*HD_, S2_, HD_, D1_, D1_, HD_, HD_,
                B_, (long)S2_*D1_, 0, 0, 0, (long)S_*HD_, 0, 1, false, EPI_NONE);

    // 5) RoPE on Q (8 heads) and K (1 head)
    {
        long nq = (long)B_ * S_ * H_ * 128;
        rope_kernel<<<(unsigned)((nq + 255) / 256), 256>>>(q, pos, H_, nq);
        long nk = (long)B_ * S_ * 1 * 128;
        rope_kernel<<<(unsigned)((nk + 255) / 256), 256>>>(k, pos, 1, nk);
    }

    // 6) scores[z=(b,h)] = Q_h @ K^T * scale, masked
    launch_gemm(q, k, scores, S_, S_, HD_, H_*HD_, HD_, S_,
                B_ * H_,
                (long)S_*H_*HD_, HD_,          // A: per-b, per-head col offset
                (long)S_*HD_, 0,               // B: per-b
                (long)H_*S_*S_, (long)S_*S_,   // C: per-b, per-head
                H_, true, EPI_SCORES,
                nullptr, 0, nullptr, 0, cs, pad_masks, S_, 0.0625f /*HD^-0.5*/);

    // 7) softmax over keys
    softmax_kernel<<<B_ * H_ * S_, 256>>>(scores);

    // 8) att[z=(b,h)] = P @ V  -> [B,S,H*HD] layout
    launch_gemm(scores, v, att, S_, HD_, S_, S_, HD_, H_*HD_,
                B_ * H_,
                (long)H_*S_*S_, (long)S_*S_,
                (long)S_*HD_, 0,
                (long)S_*H_*HD_, HD_,
                H_, false, EPI_NONE);

    // 9) output projections + residuals
    launch_gemm(att, w_o0, r0, S1_, D0_, H_*HD_, H_*HD_, D0_, D0_,
                B_, (long)S_*H_*HD_, 0, 0, 0, (long)S1_*D0_, 0, 1, false,
                EPI_RES, x0, (long)S1_*D0_);
    launch_gemm(att + (long)S1_*H_*HD_, w_o1, r1, S2_, D1_, H_*HD_, H_*HD_, D1_, D1_,
                B_, (long)S_*H_*HD_, 0, 0, 0, (long)S2_*D1_, 0, 1, false,
                EPI_RES_GATE, x1, (long)S2_*D1_, modin + D1_ /*gate_in*/, 2 * D1_);

    // 10) post norms
    rmsnorm_kernel<<<B_ * S1_, 256>>>(r0, y0, norm2_w0, 0, D0_, S1_);
    rmsnorm_kernel<<<B_ * S2_, 256>>>(r1, y1, modpost /*scale_post*/, 2 * D1_, D1_, S2_);

    // 11) MLP stream 0: gu0 = gelu(y0@Wg) * (y0@Wu); out0 = r0 + gu0@Wd
    launch_gemm(y0, w_gate0, gu0, S1_, F0_, D0_, D0_, F0_, F0_,
                B_, (long)S1_*D0_, 0, 0, 0, (long)S1_*F0_, 0, 1, false, EPI_NONE);
    launch_gemm(y0, w_up0, gu0, S1_, F0_, D0_, D0_, F0_, F0_,
                B_, (long)S1_*D0_, 0, 0, 0, (long)S1_*F0_, 0, 1, false,
                EPI_GELUMUL, gu0, (long)S1_*F0_);
    launch_gemm(gu0, w_down0, out0, S1_, D0_, F0_, F0_, D0_, D0_,
                B_, (long)S1_*F0_, 0, 0, 0, (long)S1_*D0_, 0, 1, false,
                EPI_RES, r0, (long)S1_*D0_);

    // 12) MLP stream 1: out1 = r1 + gate_post * (gu1 @ Wd1)
    launch_gemm(y1, w_gate1, gu1, S2_, F1_, D1_, D1_, F1_, F1_,
                B_, (long)S2_*D1_, 0, 0, 0, (long)S2_*F1_, 0, 1, false, EPI_NONE);
    launch_gemm(y1, w_up1, gu1, S2_, F1_, D1_, D1_, F1_, F1_,
                B_, (long)S2_*D1_, 0, 0, 0, (long)S2_*F1_, 0, 1, false,
                EPI_GELUMUL, gu1, (long)S2_*F1_);
    launch_gemm(gu1, w_down1, out1, S2_, D1_, F1_, F1_, D1_, D1_,
                B_, (long)S2_*F1_, 0, 0, 0, (long)S2_*D1_, 0, 1, false,
                EPI_RES_GATE, r1, (long)S2_*D1_, modpost + D1_ /*gate_post*/, 2 * D1_);
}

// round 3
// speedup vs baseline: 2.5672x; 2.5672x over previous
#include <cuda_runtime.h>
#include <cuda_bf16.h>
#include <math.h>
#include <stdint.h>

// ---------------- problem constants ----------------
#define B_   4
#define S1_  768
#define S2_  64
#define S_   832
#define D0_  2048
#define F0_  16384
#define D1_  1024
#define F1_  4096
#define H_   8
#define HD_  256
#define EPS_ 1e-6f
#define MASK_VAL_ -1000000000.0f

// ---------------- scratch (device globals; no allocation allowed) ----------------
__device__ float g_h0[B_*S1_*D0_];
__device__ float g_h1[B_*S2_*D1_];
__device__ float g_mod_in[B_*2*D1_];
__device__ float g_mod_post[B_*2*D1_];
__device__ float g_q[(size_t)B_*S_*H_*HD_];
__device__ float g_k[B_*S_*HD_];
__device__ float g_v[B_*S_*HD_];
__device__ float g_scores[(size_t)B_*H_*S_*S_];
__device__ float g_att[(size_t)B_*S_*H_*HD_];
__device__ float g_r0[B_*S1_*D0_];
__device__ float g_y0[B_*S1_*D0_];
__device__ float g_gu0[(size_t)B_*S1_*F0_];
__device__ float g_r1[B_*S2_*D1_];
__device__ float g_y1[B_*S2_*D1_];
__device__ float g_gu1[B_*S2_*F1_];
__device__ int   g_pos[B_*S_];
__device__ int   g_cs[B_*S_];

// split-bf16 operands (A' = [hi|hi|lo], B' = [hi|lo|hi] along K)
__device__ __nv_bfloat16 g_h03 [(size_t)3072*3*2048];
__device__ __nv_bfloat16 g_att3[(size_t)3072*3*2048];
__device__ __nv_bfloat16 g_y03 [(size_t)3072*3*2048];
__device__ __nv_bfloat16 g_gu03[(size_t)3072*3*16384];
__device__ __nv_bfloat16 g_wq03[(size_t)2048*3*2048];
__device__ __nv_bfloat16 g_wo03[(size_t)2048*3*2048];
__device__ __nv_bfloat16 g_wg03[(size_t)16384*3*2048];
__device__ __nv_bfloat16 g_wu03[(size_t)16384*3*2048];
__device__ __nv_bfloat16 g_wd03[(size_t)2048*3*16384];

// ---------------- small helpers ----------------
__device__ __forceinline__ float gelu_tanh(float x) {
    float x3 = x * x * x;
    return 0.5f * x * (1.0f + tanhf(0.79788456080286535588f * (x + 0.044715f * x3)));
}

__device__ __forceinline__ uint32_t smem_u32(const void* p) {
    uint32_t a;
    asm("{ .reg .u64 t; cvta.to.shared.u64 t, %1; cvt.u32.u64 %0, t; }" : "=r"(a) : "l"(p));
    return a;
}

#define CP_ASYNC16(sm, gm) \
    asm volatile("cp.async.cg.shared.global [%0], [%1], 16;" :: "r"(sm), "l"(gm))
#define CP_COMMIT() asm volatile("cp.async.commit_group;")
#define CP_WAIT(n)  asm volatile("cp.async.wait_group %0;" :: "n"(n))

__device__ __forceinline__ void ldsm_x4(uint32_t* r, uint32_t addr) {
    asm volatile("ldmatrix.sync.aligned.m8n8.x4.shared.b16 {%0,%1,%2,%3}, [%4];"
                 : "=r"(r[0]), "=r"(r[1]), "=r"(r[2]), "=r"(r[3]) : "r"(addr));
}
__device__ __forceinline__ void mma_bf16(float* c, const uint32_t* a, uint32_t b0, uint32_t b1) {
    asm volatile("mma.sync.aligned.m16n8k16.row.col.f32.bf16.bf16.f32 "
                 "{%0,%1,%2,%3}, {%4,%5,%6,%7}, {%8,%9}, {%0,%1,%2,%3};"
                 : "+f"(c[0]), "+f"(c[1]), "+f"(c[2]), "+f"(c[3])
                 : "r"(a[0]), "r"(a[1]), "r"(a[2]), "r"(a[3]), "r"(b0), "r"(b1));
}

// swizzled chunk address within a [rows x 64bf16] tile: row-of-8 16B chunks, chunk^(row&7)
__device__ __forceinline__ uint32_t sw_addr(uint32_t base, int row, int chunk) {
    return base + (uint32_t)(((row << 3) + (chunk ^ (row & 7))) << 4);
}

// ---------------- tensor-core split-bf16 GEMM: C[M,N] = A'[M,Kp] * B't[N,Kp]^T ----------------
#define EPI_NONE     0
#define EPI_SCORES   1
#define EPI_RES      2
#define EPI_RES_GATE 3
#define EPI_GELUMUL  4

struct TcP {
    const __nv_bfloat16* A;   // [M, Kp] row-major
    const __nv_bfloat16* Bt;  // [N, Kp] row-major (i.e. B^T)
    float* C;
    const float* aux;         // logical [M, N] row-major (EPI_RES / EPI_GELUMUL)
    int M, N, Kp;
    int epi;
    int rpb, obatch, ldc;     // out row = (r/rpb)*obatch + r%rpb
};

#define TC_STAGES 3
#define TC_STAGE_BYTES 32768     // 16KB A + 16KB B
#define TC_SMEM (TC_STAGES * TC_STAGE_BYTES)

__global__ __launch_bounds__(256) void tc_gemm_kernel(TcP p) {
    extern __shared__ char dsm[];
    uint32_t sbase = smem_u32(dsm);

    int tid  = threadIdx.x;
    int wid  = tid >> 5;
    int lane = tid & 31;
    int wm = wid >> 2;          // 0..1 -> row offset wm*64
    int wn = wid & 3;           // 0..3 -> col offset wn*32

    int m0 = blockIdx.y * 128;
    int n0 = blockIdx.x * 128;

    // per-thread cp.async coords: chunk kc fixed, rows r + {0,32,64,96}
    int kc   = tid & 7;
    int rb   = tid >> 3;        // 0..31
    const __nv_bfloat16* gA = p.A  + (size_t)(m0) * p.Kp + kc * 8;
    const __nv_bfloat16* gB = p.Bt + (size_t)(n0) * p.Kp + kc * 8;

    float acc[4][4][4];
    #pragma unroll
    for (int i = 0; i < 4; i++)
        #pragma unroll
        for (int j = 0; j < 4; j++)
            #pragma unroll
            for (int e = 0; e < 4; e++) acc[i][j][e] = 0.f;

    int nIter = p.Kp >> 6;

    // ---- issue one stage's loads ----
    auto issue = [&](int it) {
        int st = it % TC_STAGES;
        uint32_t sa = sbase + st * TC_STAGE_BYTES;
        uint32_t sb = sa + 16384;
        int k0 = it << 6;
        #pragma unroll
        for (int i = 0; i < 4; i++) {
            int row = rb + i * 32;
            CP_ASYNC16(sw_addr(sa, row, kc), gA + (size_t)row * p.Kp + k0);
            CP_ASYNC16(sw_addr(sb, row, kc), gB + (size_t)row * p.Kp + k0);
        }
        CP_COMMIT();
    };

    #pragma unroll
    for (int s = 0; s < TC_STAGES - 1; s++) issue(s);

    int grp = lane >> 3;     // 0..3
    int lr  = lane & 7;

    for (int it = 0; it < nIter; it++) {
        if (it + TC_STAGES - 1 < nIter) {
            issue(it + TC_STAGES - 1);
            CP_WAIT(TC_STAGES - 2);
        } else {
            CP_WAIT(0);
        }
        __syncthreads();

        int st = it % TC_STAGES;
        uint32_t sa = sbase + st * TC_STAGE_BYTES;
        uint32_t sb = sa + 16384;

        #pragma unroll
        for (int kb = 0; kb < 4; kb++) {
            int chA = 2 * kb + (grp >> 1);
            uint32_t a[4][4];
            #pragma unroll
            for (int mi = 0; mi < 4; mi++) {
                int row = wm * 64 + mi * 16 + (grp & 1) * 8 + lr;
                ldsm_x4(a[mi], sw_addr(sa, row, chA));
            }
            uint32_t bf[2][4];
            #pragma unroll
            for (int bi = 0; bi < 2; bi++) {
                int row = wn * 32 + bi * 16 + (grp & 1) * 8 + lr;
                ldsm_x4(bf[bi], sw_addr(sb, row, chA));
            }
            #pragma unroll
            for (int mi = 0; mi < 4; mi++)
                #pragma unroll
                for (int ni = 0; ni < 4; ni++) {
                    int bi = ni >> 1, wh = ni & 1;
                    mma_bf16(acc[mi][ni], a[mi], bf[bi][wh], bf[bi][wh + 2]);
                }
        }
        __syncthreads();
    }

    // ---- epilogue ----
    int qrow = lane >> 2;        // 0..7
    int qcol = (lane & 3) * 2;
    #pragma unroll
    for (int mi = 0; mi < 4; mi++) {
        #pragma unroll
        for (int half = 0; half < 2; half++) {
            int r = m0 + wm * 64 + mi * 16 + half * 8 + qrow;
            int orow = (r / p.rpb) * p.obatch + (r % p.rpb);
            #pragma unroll
            for (int ni = 0; ni < 4; ni++) {
                int col = n0 + wn * 32 + ni * 8 + qcol;
                float v0 = acc[mi][ni][half * 2 + 0];
                float v1 = acc[mi][ni][half * 2 + 1];
                if (p.epi == EPI_RES) {
                    float2 ax = *(const float2*)&p.aux[(size_t)r * p.N + col];
                    v0 += ax.x; v1 += ax.y;
                } else if (p.epi == EPI_GELUMUL) {
                    float2 ax = *(const float2*)&p.aux[(size_t)r * p.N + col];
                    v0 = gelu_tanh(ax.x) * v0;
                    v1 = gelu_tanh(ax.y) * v1;
                }
                float2 o = make_float2(v0, v1);
                *(float2*)&p.C[(size_t)orow * p.ldc + col] = o;
            }
        }
    }
}

// ---------------- split conversion kernels ----------------
// activations: out[r, 0..K)=hi, [K..2K)=hi, [2K..3K)=lo ; in row = (r/rpb)*ibatch + r%rpb
__global__ void split_act_kernel(const float* __restrict__ in, __nv_bfloat16* __restrict__ out,
                                 int M, int K, int rpb, int ibatch) {
    size_t idx = blockIdx.x * (size_t)blockDim.x + threadIdx.x;
    size_t total = (size_t)M * K;
    if (idx >= total) return;
    int r = (int)(idx / K), k = (int)(idx % K);
    int ir = (r / rpb) * ibatch + (r % rpb);
    float v = in[(size_t)ir * K + k];
    __nv_bfloat16 hi = __float2bfloat16(v);
    __nv_bfloat16 lo = __float2bfloat16(v - __bfloat162float(hi));
    __nv_bfloat16* o = out + (size_t)r * 3 * K;
    o[k] = hi; o[K + k] = hi; o[2 * K + k] = lo;
}

// weights W[K,N] -> out[N, 3K]: [0..K)=hi, [K..2K)=lo, [2K..3K)=hi (transposed)
__global__ void tsplit_kernel(const float* __restrict__ W, __nv_bfloat16* __restrict__ out,
                              int K, int N) {
    __shared__ float t[32][33];
    int k0 = blockIdx.y * 32, n0 = blockIdx.x * 32;
    int tx = threadIdx.x, ty = threadIdx.y;   // 32 x 8
    #pragma unroll
    for (int i = 0; i < 4; i++)
        t[ty + i * 8][tx] = W[(size_t)(k0 + ty + i * 8) * N + n0 + tx];
    __syncthreads();
    #pragma unroll
    for (int i = 0; i < 4; i++) {
        int n = n0 + ty + i * 8;
        int k = k0 + tx;
        float v = t[tx][ty + i * 8];
        __nv_bfloat16 hi = __float2bfloat16(v);
        __nv_bfloat16 lo = __float2bfloat16(v - __bfloat162float(hi));
        __nv_bfloat16* o = out + (size_t)n * 3 * K;
        o[k] = hi; o[K + k] = lo; o[2 * K + k] = hi;
    }
}

// ---------------- legacy FFMA batched SGEMM (small ops / attention) ----------------
struct GemmP {
    const float* A; const float* B; float* C;
    int M, N, K, lda, ldb, ldc;
    long sA1, sA2, sB1, sB2, sC1, sC2;
    int zdiv;
    int transB;
    int epi;
    const float* aux; long sAux;
    const float* gvec; int gvecStride;
    const int* cs; const int* pad; int maskStride;
    float scale;
};

#define BM 128
#define BN 128
#define BK 8
#define TM 8
#define TN 8

__global__ __launch_bounds__(256) void gemm_kernel(GemmP p) {
    __shared__ float As[BK][BM];
    __shared__ float Bs[BK][BN];

    int z  = blockIdx.z;
    int zb = z / p.zdiv;
    int zr = z % p.zdiv;

    const float* A = p.A + (long)zb * p.sA1 + (long)zr * p.sA2;
    const float* Bm = p.B + (long)zb * p.sB1 + (long)zr * p.sB2;
    float* C = p.C + (long)zb * p.sC1 + (long)zr * p.sC2;

    int rowBase = blockIdx.y * BM;
    int colBase = blockIdx.x * BN;
    int tid = threadIdx.x;
    int tx = tid % 16;
    int ty = tid / 16;

    float acc[TM][TN];
    #pragma unroll
    for (int i = 0; i < TM; i++)
        #pragma unroll
        for (int j = 0; j < TN; j++) acc[i][j] = 0.0f;

    int aRow = tid >> 1;
    int aCol = (tid & 1) * 4;
    int bRow = tid >> 5;
    int bCol = (tid & 31) * 4;

    for (int k0 = 0; k0 < p.K; k0 += BK) {
        {
            int gr = rowBase + aRow;
            float4 av = make_float4(0.f, 0.f, 0.f, 0.f);
            if (gr < p.M)
                av = *(const float4*)&A[(long)gr * p.lda + k0 + aCol];
            As[aCol + 0][aRow] = av.x;
            As[aCol + 1][aRow] = av.y;
            As[aCol + 2][aRow] = av.z;
            As[aCol + 3][aRow] = av.w;
        }
        if (!p.transB) {
            int gk = k0 + bRow;
            int gc = colBase + bCol;
            if (gc + 3 < p.N) {
                float4 bv = *(const float4*)&Bm[(long)gk * p.ldb + gc];
                Bs[bRow][bCol + 0] = bv.x;
                Bs[bRow][bCol + 1] = bv.y;
                Bs[bRow][bCol + 2] = bv.z;
                Bs[bRow][bCol + 3] = bv.w;
            } else {
                #pragma unroll
                for (int i = 0; i < 4; i++)
                    Bs[bRow][bCol + i] = (gc + i < p.N) ? Bm[(long)gk * p.ldb + gc + i] : 0.f;
            }
        } else {
            int n  = tid >> 1;
            int kk = (tid & 1) * 4;
            int gn = colBase + n;
            float4 bv = make_float4(0.f, 0.f, 0.f, 0.f);
            if (gn < p.N)
                bv = *(const float4*)&Bm[(long)gn * p.ldb + k0 + kk];
            Bs[kk + 0][n] = bv.x;
            Bs[kk + 1][n] = bv.y;
            Bs[kk + 2][n] = bv.z;
            Bs[kk + 3][n] = bv.w;
        }
        __syncthreads();

        #pragma unroll
        for (int k = 0; k < BK; k++) {
            float a[TM], b[TN];
            float4 a0 = *(const float4*)&As[k][ty * TM];
            float4 a1 = *(const float4*)&As[k][ty * TM + 4];
            a[0]=a0.x; a[1]=a0.y; a[2]=a0.z; a[3]=a0.w;
            a[4]=a1.x; a[5]=a1.y; a[6]=a1.z; a[7]=a1.w;
            float4 b0 = *(const float4*)&Bs[k][tx * TN];
            float4 b1 = *(const float4*)&Bs[k][tx * TN + 4];
            b[0]=b0.x; b[1]=b0.y; b[2]=b0.z; b[3]=b0.w;
            b[4]=b1.x; b[5]=b1.y; b[6]=b1.z; b[7]=b1.w;
            #pragma unroll
            for (int i = 0; i < TM; i++)
                #pragma unroll
                for (int j = 0; j < TN; j++)
                    acc[i][j] += a[i] * b[j];
        }
        __syncthreads();
    }

    const int* csb  = p.cs  ? p.cs  + (long)zb * p.maskStride : nullptr;
    const int* padb = p.pad ? p.pad + (long)zb * p.maskStride : nullptr;
    long auxOff = (long)zb * p.sAux;

    #pragma unroll
    for (int i = 0; i < TM; i++) {
        int row = rowBase + ty * TM + i;
        if (row >= p.M) continue;
        #pragma unroll
        for (int j = 0; j < TN; j++) {
            int col = colBase + tx * TN + j;
            if (col >= p.N) continue;
            long idx = (long)row * p.ldc + col;
            float v = acc[i][j];
            if (p.epi == EPI_SCORES) {
                bool ok = (csb[col] <= csb[row]) && (padb[row] != 0) && (padb[col] != 0);
                v = ok ? v * p.scale : MASK_VAL_;
            } else if (p.epi == EPI_RES) {
                v += p.aux[auxOff + idx];
            } else if (p.epi == EPI_RES_GATE) {
                v = p.aux[auxOff + idx] + p.gvec[(long)zb * p.gvecStride + col] * v;
            } else if (p.epi == EPI_GELUMUL) {
                v = gelu_tanh(p.aux[auxOff + idx]) * v;
            }
            C[idx] = v;
        }
    }
}

// ---------------- mod GEMV ----------------
__global__ void mod_kernel(const float* __restrict__ cond, const float* __restrict__ W,
                           const float* __restrict__ bias, float* __restrict__ out,
                           int D, int N) {
    int j = blockIdx.x * blockDim.x + threadIdx.x;
    int b = blockIdx.y;
    if (j >= N) return;
    float s = bias[j];
    const float* c = cond + (long)b * D;
    for (int k = 0; k < D; k++)
        s += c[k] * W[(long)k * N + j];
    out[(long)b * N + j] = s;
}

// ---------------- prefix scans ----------------
__global__ void scan_kernel(const int* __restrict__ pad, const int* __restrict__ att,
                            int* __restrict__ pos, int* __restrict__ cs) {
    int b = threadIdx.x;
    if (b >= B_) return;
    int cp = 0, ca = 0;
    for (int s = 0; s < S_; s++) {
        cp += pad[b * S_ + s];
        ca += att[b * S_ + s];
        pos[b * S_ + s] = cp - 1;
        cs[b * S_ + s] = ca;
    }
}

// ---------------- RMSNorm ----------------
__global__ void rmsnorm_kernel(const float* __restrict__ x, float* __restrict__ out,
                               const float* __restrict__ w, int wStride,
                               int D, int rowsPerBatch) {
    long row = blockIdx.x;
    int b = (int)(row / rowsPerBatch);
    const float* xp = x + row * (long)D;
    float ss = 0.f;
    for (int i = threadIdx.x; i < D; i += blockDim.x) {
        float v = xp[i];
        ss += v * v;
    }
    __shared__ float red[256];
    red[threadIdx.x] = ss;
    __syncthreads();
    for (int s = 128; s > 0; s >>= 1) {
        if (threadIdx.x < s) red[threadIdx.x] += red[threadIdx.x + s];
        __syncthreads();
    }
    float r = rsqrtf(red[0] / (float)D + EPS_);
    const float* wp = w + (long)b * wStride;
    float* op = out + row * (long)D;
    for (int i = threadIdx.x; i < D; i += blockDim.x)
        op[i] = xp[i] * r * (1.0f + wp[i]);
}

// ---------------- RoPE ----------------
__global__ void rope_kernel(float* __restrict__ X, const int* __restrict__ pos, int nH, long total) {
    long idx = blockIdx.x * (long)blockDim.x + threadIdx.x;
    if (idx >= total) return;
    int i = (int)(idx & 127);
    long t = idx >> 7;
    int h = (int)(t % nH); t /= nH;
    int s = (int)(t % S_);
    int b = (int)(t / S_);
    float p = (float)pos[b * S_ + s];
    float inv = expf(-((float)i / 128.0f) * 9.210340371976184f);
    float f = p * inv;
    float c = cosf(f), sn = sinf(f);
    float* base = X + ((long)(b * S_ + s) * nH + h) * (long)HD_;
    float x1 = base[i];
    float x2 = base[i + 128];
    base[i]       = x1 * c - x2 * sn;
    base[i + 128] = x2 * c + x1 * sn;
}

// ---------------- row softmax ----------------
__global__ void softmax_kernel(float* __restrict__ scores) {
    float* p = scores + (long)blockIdx.x * S_;
    __shared__ float red[256];
    int tid = threadIdx.x;

    float m = -3.4e38f;
    for (int i = tid; i < S_; i += 256) m = fmaxf(m, p[i]);
    red[tid] = m;
    __syncthreads();
    for (int s = 128; s > 0; s >>= 1) {
        if (tid < s) red[tid] = fmaxf(red[tid], red[tid + s]);
        __syncthreads();
    }
    m = red[0];
    __syncthreads();

    float sum = 0.f;
    for (int i = tid; i < S_; i += 256) {
        float e = expf(p[i] - m);
        p[i] = e;
        sum += e;
    }
    red[tid] = sum;
    __syncthreads();
    for (int s = 128; s > 0; s >>= 1) {
        if (tid < s) red[tid] += red[tid + s];
        __syncthreads();
    }
    float inv = 1.0f / red[0];
    for (int i = tid; i < S_; i += 256) p[i] *= inv;
}

// ---------------- host helpers ----------------
static void launch_gemm(const float* A, const float* Bm, float* C,
                        int M, int N, int K, int lda, int ldb, int ldc,
                        int batches, long sA1, long sA2, long sB1, long sB2,
                        long sC1, long sC2, int zdiv, bool transB, int epi,
                        const float* aux = nullptr, long sAux = 0,
                        const float* gvec = nullptr, int gvecStride = 0,
                        const int* cs = nullptr, const int* pad = nullptr,
                        int maskStride = 0, float scale = 1.0f) {
    GemmP p;
    p.A = A; p.B = Bm; p.C = C;
    p.M = M; p.N = N; p.K = K; p.lda = lda; p.ldb = ldb; p.ldc = ldc;
    p.sA1 = sA1; p.sA2 = sA2; p.sB1 = sB1; p.sB2 = sB2; p.sC1 = sC1; p.sC2 = sC2;
    p.zdiv = zdiv; p.transB = transB ? 1 : 0; p.epi = epi;
    p.aux = aux; p.sAux = sAux; p.gvec = gvec; p.gvecStride = gvecStride;
    p.cs = cs; p.pad = pad; p.maskStride = maskStride; p.scale = scale;
    dim3 grid((N + BN - 1) / BN, (M + BM - 1) / BM, batches);
    gemm_kernel<<<grid, 256>>>(p);
}

static void launch_tc(const __nv_bfloat16* A, const __nv_bfloat16* Bt, float* C,
                      int M, int N, int Kp, int epi, const float* aux,
                      int rpb, int obatch, int ldc) {
    static bool attrSet = false;
    if (!attrSet) {
        cudaFuncSetAttribute(tc_gemm_kernel, cudaFuncAttributeMaxDynamicSharedMemorySize, TC_SMEM);
        attrSet = true;
    }
    TcP p;
    p.A = A; p.Bt = Bt; p.C = C; p.aux = aux;
    p.M = M; p.N = N; p.Kp = Kp; p.epi = epi;
    p.rpb = rpb; p.obatch = obatch; p.ldc = ldc;
    dim3 grid(N / 128, M / 128);
    tc_gemm_kernel<<<grid, 256, TC_SMEM>>>(p);
}

static void launch_split(const float* in, __nv_bfloat16* out, int M, int K, int rpb, int ibatch) {
    size_t total = (size_t)M * K;
    split_act_kernel<<<(unsigned)((total + 255) / 256), 256>>>(in, out, M, K, rpb, ibatch);
}

static void launch_tsplit(const float* W, __nv_bfloat16* out, int K, int N) {
    dim3 grid(N / 32, K / 32);
    tsplit_kernel<<<grid, dim3(32, 8)>>>(W, out, K, N);
}

extern "C" void kernel_launch(void* const* d_in, const int* in_sizes, int n_in,
                              void* d_out, int out_size) {
    const float* x0         = (const float*)d_in[0];
    const float* x1         = (const float*)d_in[1];
    const float* cond1      = (const float*)d_in[2];
    const float* w_q0       = (const float*)d_in[3];
    const float* w_k0       = (const float*)d_in[4];
    const float* w_v0       = (const float*)d_in[5];
    const float* w_o0       = (const float*)d_in[6];
    const float* norm1_w0   = (const float*)d_in[7];
    const float* norm2_w0   = (const float*)d_in[8];
    const float* w_gate0    = (const float*)d_in[9];
    const float* w_up0      = (const float*)d_in[10];
    const float* w_down0    = (const float*)d_in[11];
    const float* w_q1       = (const float*)d_in[12];
    const float* w_k1       = (const float*)d_in[13];
    const float* w_v1       = (const float*)d_in[14];
    const float* w_o1       = (const float*)d_in[15];
    const float* ada_in_w1  = (const float*)d_in[16];
    const float* ada_in_b1  = (const float*)d_in[17];
    const float* ada_post_w1= (const float*)d_in[18];
    const float* ada_post_b1= (const float*)d_in[19];
    const float* w_gate1    = (const float*)d_in[20];
    const float* w_up1      = (const float*)d_in[21];
    const float* w_down1    = (const float*)d_in[22];
    const int*   pad_masks  = (const int*)d_in[23];
    const int*   att_masks  = (const int*)d_in[24];

    float* out0 = (float*)d_out;
    float* out1 = out0 + (size_t)B_ * S1_ * D0_;

    float *h0, *h1, *modin, *modpost, *q, *k, *v, *scores, *att, *r0, *y0, *gu0, *r1, *y1, *gu1;
    int *pos, *cs;
    __nv_bfloat16 *h03, *att3, *y03, *gu03, *wq03, *wo03, *wg03, *wu03, *wd03;
    cudaGetSymbolAddress((void**)&h0, g_h0);
    cudaGetSymbolAddress((void**)&h1, g_h1);
    cudaGetSymbolAddress((void**)&modin, g_mod_in);
    cudaGetSymbolAddress((void**)&modpost, g_mod_post);
    cudaGetSymbolAddress((void**)&q, g_q);
    cudaGetSymbolAddress((void**)&k, g_k);
    cudaGetSymbolAddress((void**)&v, g_v);
    cudaGetSymbolAddress((void**)&scores, g_scores);
    cudaGetSymbolAddress((void**)&att, g_att);
    cudaGetSymbolAddress((void**)&r0, g_r0);
    cudaGetSymbolAddress((void**)&y0, g_y0);
    cudaGetSymbolAddress((void**)&gu0, g_gu0);
    cudaGetSymbolAddress((void**)&r1, g_r1);
    cudaGetSymbolAddress((void**)&y1, g_y1);
    cudaGetSymbolAddress((void**)&gu1, g_gu1);
    cudaGetSymbolAddress((void**)&pos, g_pos);
    cudaGetSymbolAddress((void**)&cs, g_cs);
    cudaGetSymbolAddress((void**)&h03, g_h03);
    cudaGetSymbolAddress((void**)&att3, g_att3);
    cudaGetSymbolAddress((void**)&y03, g_y03);
    cudaGetSymbolAddress((void**)&gu03, g_gu03);
    cudaGetSymbolAddress((void**)&wq03, g_wq03);
    cudaGetSymbolAddress((void**)&wo03, g_wo03);
    cudaGetSymbolAddress((void**)&wg03, g_wg03);
    cudaGetSymbolAddress((void**)&wu03, g_wu03);
    cudaGetSymbolAddress((void**)&wd03, g_wd03);

    const int M0 = B_ * S1_;   // 3072

    // weight prep (split + transpose to [N, 3K])
    launch_tsplit(w_q0,    wq03, D0_, H_ * HD_);
    launch_tsplit(w_o0,    wo03, H_ * HD_, D0_);
    launch_tsplit(w_gate0, wg03, D0_, F0_);
    launch_tsplit(w_up0,   wu03, D0_, F0_);
    launch_tsplit(w_down0, wd03, F0_, D0_);

    // 1) adaLN modulation
    {
        dim3 mg((2 * D1_ + 255) / 256, B_);
        mod_kernel<<<mg, 256>>>(cond1, ada_in_w1,  ada_in_b1,  modin,   D1_, 2 * D1_);
        mod_kernel<<<mg, 256>>>(cond1, ada_post_w1, ada_post_b1, modpost, D1_, 2 * D1_);
    }

    // 2) scans
    scan_kernel<<<1, 32>>>(pad_masks, att_masks, pos, cs);

    // 3) input norms
    rmsnorm_kernel<<<B_ * S1_, 256>>>(x0, h0, norm1_w0, 0, D0_, S1_);
    rmsnorm_kernel<<<B_ * S2_, 256>>>(x1, h1, modin, 2 * D1_, D1_, S2_);

    // 4) QKV stream 0: q via tensor cores (remap rows into S=832 buffer), k/v small FFMA
    launch_split(h0, h03, M0, D0_, M0, 0);
    launch_tc(h03, wq03, q, M0, H_ * HD_, 3 * D0_, EPI_NONE, nullptr, S1_, S_, H_ * HD_);
    launch_gemm(h0, w_k0, k, S1_, HD_, D0_, D0_, HD_, HD_,
                B_, (long)S1_*D0_, 0, 0, 0, (long)S_*HD_, 0, 1, false, EPI_NONE);
    launch_gemm(h0, w_v0, v, S1_, HD_, D0_, D0_, HD_, HD_,
                B_, (long)S1_*D0_, 0, 0, 0, (long)S_*HD_, 0, 1, false, EPI_NONE);
    launch_gemm(h1, w_q1, q + (long)S1_*H_*HD_, S2_, H_*HD_, D1_, D1_, H_*HD_, H_*HD_,
                B_, (long)S2_*D1_, 0, 0, 0, (long)S_*H_*HD_, 0, 1, false, EPI_NONE);
    launch_gemm(h1, w_k1, k + (long)S1_*HD_, S2_, HD_, D1_, D1_, HD_, HD_,
                B_, (long)S2_*D1_, 0, 0, 0, (long)S_*HD_, 0, 1, false, EPI_NONE);
    launch_gemm(h1, w_v1, v + (long)S1_*HD_, S2_, HD_, D1_, D1_, HD_, HD_,
                B_, (long)S2_*D1_, 0, 0, 0, (long)S_*HD_, 0, 1, false, EPI_NONE);

    // 5) RoPE
    {
        long nq = (long)B_ * S_ * H_ * 128;
        rope_kernel<<<(unsigned)((nq + 255) / 256), 256>>>(q, pos, H_, nq);
        long nk = (long)B_ * S_ * 1 * 128;
        rope_kernel<<<(unsigned)((nk + 255) / 256), 256>>>(k, pos, 1, nk);
    }

    // 6) scores, 7) softmax, 8) att (FFMA path)
    launch_gemm(q, k, scores, S_, S_, HD_, H_*HD_, HD_, S_,
                B_ * H_,
                (long)S_*H_*HD_, HD_,
                (long)S_*HD_, 0,
                (long)H_*S_*S_, (long)S_*S_,
                H_, true, EPI_SCORES,
                nullptr, 0, nullptr, 0, cs, pad_masks, S_, 0.0625f);
    softmax_kernel<<<B_ * H_ * S_, 256>>>(scores);
    launch_gemm(scores, v, att, S_, HD_, S_, S_, HD_, H_*HD_,
                B_ * H_,
                (long)H_*S_*S_, (long)S_*S_,
                (long)S_*HD_, 0,
                (long)S_*H_*HD_, HD_,
                H_, false, EPI_NONE);

    // 9) output projections
    launch_split(att, att3, M0, H_ * HD_, S1_, S_);   // gather first 768 rows of each batch
    launch_tc(att3, wo03, r0, M0, D0_, 3 * H_ * HD_, EPI_RES, x0, M0, 0, D0_);
    launch_gemm(att + (long)S1_*H_*HD_, w_o1, r1, S2_, D1_, H_*HD_, H_*HD_, D1_, D1_,
                B_, (long)S_*H_*HD_, 0, 0, 0, (long)S2_*D1_, 0, 1, false,
                EPI_RES_GATE, x1, (long)S2_*D1_, modin + D1_, 2 * D1_);

    // 10) post norms
    rmsnorm_kernel<<<B_ * S1_, 256>>>(r0, y0, norm2_w0, 0, D0_, S1_);
    rmsnorm_kernel<<<B_ * S2_, 256>>>(r1, y1, modpost, 2 * D1_, D1_, S2_);

    // 11) MLP stream 0 (tensor cores)
    launch_split(y0, y03, M0, D0_, M0, 0);
    launch_tc(y03, wg03, gu0, M0, F0_, 3 * D0_, EPI_NONE, nullptr, M0, 0, F0_);
    launch_tc(y03, wu03, gu0, M0, F0_, 3 * D0_, EPI_GELUMUL, gu0, M0, 0, F0_);
    launch_split(gu0, gu03, M0, F0_, M0, 0);
    launch_tc(gu03, wd03, out0, M0, D0_, 3 * F0_, EPI_RES, r0, M0, 0, D0_);

    // 12) MLP stream 1 (FFMA)
    launch_gemm(y1, w_gate1, gu1, S2_, F1_, D1_, D1_, F1_, F1_,
                B_, (long)S2_*D1_, 0, 0, 0, (long)S2_*F1_, 0, 1, false, EPI_NONE);
    launch_gemm(y1, w_up1, gu1, S2_, F1_, D1_, D1_, F1_, F1_,
                B_, (long)S2_*D1_, 0, 0, 0, (long)S2_*F1_, 0, 1, false,
                EPI_GELUMUL, gu1, (long)S2_*F1_);
    launch_gemm(gu1, w_down1, out1, S2_, D1_, F1_, F1_, D1_, D1_,
                B_, (long)S2_*F1_, 0, 0, 0, (long)S2_*D1_, 0, 1, false,
                EPI_RES_GATE, r1, (long)S2_*D1_, modpost + D1_, 2 * D1_);
}